// round 4
// baseline (speedup 1.0000x reference)
#include <cuda_runtime.h>
#include <cstdint>
#include <math.h>

#define Tn 4096   // B*S tokens
#define Dn 1024
#define Hn 4096
#define En 8
#define NSn 2

// Compact scratch: routed hidden rows sum to exactly 2*Tn (top-2 routing),
// shared experts use NSn*Tn rows. Total (2+NSn)*Tn*Hn floats = 256 MB.
#define ROUTED_ROWS (2 * Tn)
__device__ float g_h[(size_t)(ROUTED_ROWS + NSn * Tn) * Hn];
__device__ int   g_cnt[En];
__device__ int   g_off[En];     // exclusive prefix of g_cnt
__device__ int   g_list[En * Tn];

__device__ __forceinline__ float gelu_f(float v) {
    // jax.nn.gelu default (approximate=True, tanh form)
    float u = 0.7978845608028654f * (v + 0.044715f * v * v * v);
    return 0.5f * v * (1.0f + tanhf(u));
}

__global__ void zero_cnt_kernel() {
    if (threadIdx.x < En) g_cnt[threadIdx.x] = 0;
}

// Exclusive prefix-sum of the 8 counts (single thread; trivial).
__global__ void prefix_kernel() {
    if (threadIdx.x == 0) {
        int s = 0;
#pragma unroll
        for (int e = 0; e < En; e++) { g_off[e] = s; s += g_cnt[e]; }
    }
}

// One block per token: logits = x@Wr + br + gumbel; top-2 (softmax is monotone,
// so top-k of softmax((l+g)/T) == top-2 of (l+g)). Scatter token into expert lists.
__global__ void router_kernel(const float* __restrict__ x,
                              const float* __restrict__ Wr,
                              const float* __restrict__ br,
                              const float* __restrict__ gum) {
    int t = blockIdx.x;
    int tid = threadIdx.x;  // 128 threads
    const float* xr = x + (size_t)t * Dn;
    float acc[En];
#pragma unroll
    for (int e = 0; e < En; e++) acc[e] = 0.f;
    for (int d = tid; d < Dn; d += 128) {
        float xv = xr[d];
        float4 w0 = *(const float4*)(Wr + d * En);
        float4 w1 = *(const float4*)(Wr + d * En + 4);
        acc[0] += xv * w0.x; acc[1] += xv * w0.y;
        acc[2] += xv * w0.z; acc[3] += xv * w0.w;
        acc[4] += xv * w1.x; acc[5] += xv * w1.y;
        acc[6] += xv * w1.z; acc[7] += xv * w1.w;
    }
#pragma unroll
    for (int e = 0; e < En; e++) {
#pragma unroll
        for (int off = 16; off; off >>= 1)
            acc[e] += __shfl_down_sync(0xffffffffu, acc[e], off);
    }
    __shared__ float red[4][En];
    if ((tid & 31) == 0) {
#pragma unroll
        for (int e = 0; e < En; e++) red[tid >> 5][e] = acc[e];
    }
    __syncthreads();
    if (tid == 0) {
        float s[En];
#pragma unroll
        for (int e = 0; e < En; e++)
            s[e] = red[0][e] + red[1][e] + red[2][e] + red[3][e]
                 + br[e] + gum[(size_t)t * En + e];
        int i1 = 0;
#pragma unroll
        for (int e = 1; e < En; e++) if (s[e] > s[i1]) i1 = e;   // ties -> lower idx (matches top_k)
        int i2 = (i1 == 0) ? 1 : 0;
#pragma unroll
        for (int e = 0; e < En; e++)
            if (e != i1 && s[e] > s[i2]) i2 = e;
        int p1 = atomicAdd(&g_cnt[i1], 1); g_list[i1 * Tn + p1] = t;
        int p2 = atomicAdd(&g_cnt[i2], 1); g_list[i2 * Tn + p2] = t;
    }
}

// ---------------- GEMM 1: H[i,:] = gelu(Xg[i,:] @ W1[z] + b1[z]) ----------------
// Tiles: BM=BN=128, BK=16, 256 threads, 8x8 per thread.
// Hidden row for routed expert z, local row r lives at g_h[(g_off[z]+r)*Hn].
// Shared expert z uses rows ROUTED_ROWS + z*Tn + r.
template <bool GATHER>
__global__ void __launch_bounds__(256)
ffn1_k(const float* __restrict__ X, const float* __restrict__ W1,
       const float* __restrict__ b1) {
    const int KD = Dn, ND = Hn;
    int z = blockIdx.z;
    int M = GATHER ? g_cnt[z] : Tn;
    int m0 = blockIdx.y * 128;
    if (m0 >= M) return;
    int n0 = blockIdx.x * 128;
    int tid = threadIdx.x;

    __shared__ __align__(16) float As[16][128];
    __shared__ __align__(16) float Bs[16][128];
    float acc[8][8];
#pragma unroll
    for (int i = 0; i < 8; i++)
#pragma unroll
        for (int j = 0; j < 8; j++) acc[i][j] = 0.f;

    int ar = tid >> 1, ac = (tid & 1) * 8;
    int arow = m0 + ar;
    int grow = 0;
    if (arow < M) grow = GATHER ? g_list[z * Tn + arow] : arow;
    const float* Arow = X + (size_t)grow * KD;
    const float* Bptr = W1 + (size_t)z * KD * ND
                           + (size_t)(tid >> 4) * ND + n0 + (tid & 15) * 8;
    int brw = tid >> 4, bcol = (tid & 15) * 8;
    int tx = tid & 15, ty = tid >> 4;

    for (int k0 = 0; k0 < KD; k0 += 16) {
        float4 a0 = *(const float4*)(Arow + k0 + ac);
        float4 a1 = *(const float4*)(Arow + k0 + ac + 4);
        float4 bb0 = *(const float4*)(Bptr + (size_t)k0 * ND);
        float4 bb1 = *(const float4*)(Bptr + (size_t)k0 * ND + 4);
        As[ac + 0][ar] = a0.x; As[ac + 1][ar] = a0.y;
        As[ac + 2][ar] = a0.z; As[ac + 3][ar] = a0.w;
        As[ac + 4][ar] = a1.x; As[ac + 5][ar] = a1.y;
        As[ac + 6][ar] = a1.z; As[ac + 7][ar] = a1.w;
        *(float4*)&Bs[brw][bcol]     = bb0;
        *(float4*)&Bs[brw][bcol + 4] = bb1;
        __syncthreads();
#pragma unroll
        for (int kk = 0; kk < 16; kk++) {
            float a[8], b[8];
            *(float4*)&a[0] = *(const float4*)&As[kk][ty * 8];
            *(float4*)&a[4] = *(const float4*)&As[kk][ty * 8 + 4];
            *(float4*)&b[0] = *(const float4*)&Bs[kk][tx * 8];
            *(float4*)&b[4] = *(const float4*)&Bs[kk][tx * 8 + 4];
#pragma unroll
            for (int i = 0; i < 8; i++)
#pragma unroll
                for (int j = 0; j < 8; j++) acc[i][j] += a[i] * b[j];
        }
        __syncthreads();
    }

    size_t rowBase = GATHER ? (size_t)g_off[z] : (size_t)(ROUTED_ROWS + z * Tn);
    const float* bz = b1 + (size_t)z * ND + n0 + tx * 8;
#pragma unroll
    for (int i = 0; i < 8; i++) {
        int r = m0 + ty * 8 + i;
        if (r < M) {
            float* hr = g_h + (rowBase + r) * Hn + n0 + tx * 8;
#pragma unroll
            for (int j = 0; j < 8; j++) hr[j] = gelu_f(acc[i][j] + bz[j]);
        }
    }
}

// ---------------- GEMM 2: out[tok,:] += H[i,:] @ W2[z] + b2[z] ----------------
template <bool GATHER>
__global__ void __launch_bounds__(256)
ffn2_k(const float* __restrict__ W2, const float* __restrict__ b2,
       float* __restrict__ out) {
    const int KD = Hn, ND = Dn;
    int z = blockIdx.z;
    int M = GATHER ? g_cnt[z] : Tn;
    int m0 = blockIdx.y * 128;
    if (m0 >= M) return;
    int n0 = blockIdx.x * 128;
    int tid = threadIdx.x;

    __shared__ __align__(16) float As[16][128];
    __shared__ __align__(16) float Bs[16][128];
    float acc[8][8];
#pragma unroll
    for (int i = 0; i < 8; i++)
#pragma unroll
        for (int j = 0; j < 8; j++) acc[i][j] = 0.f;

    size_t rowBase = GATHER ? (size_t)g_off[z] : (size_t)(ROUTED_ROWS + z * Tn);
    const float* X = g_h + rowBase * Hn;
    int ar = tid >> 1, ac = (tid & 1) * 8;
    int arow = m0 + ar;
    int r_ld = (arow < M) ? arow : 0;
    const float* Arow = X + (size_t)r_ld * KD;
    const float* Bptr = W2 + (size_t)z * KD * ND
                           + (size_t)(tid >> 4) * ND + n0 + (tid & 15) * 8;
    int brw = tid >> 4, bcol = (tid & 15) * 8;
    int tx = tid & 15, ty = tid >> 4;

    for (int k0 = 0; k0 < KD; k0 += 16) {
        float4 a0 = *(const float4*)(Arow + k0 + ac);
        float4 a1 = *(const float4*)(Arow + k0 + ac + 4);
        float4 bb0 = *(const float4*)(Bptr + (size_t)k0 * ND);
        float4 bb1 = *(const float4*)(Bptr + (size_t)k0 * ND + 4);
        As[ac + 0][ar] = a0.x; As[ac + 1][ar] = a0.y;
        As[ac + 2][ar] = a0.z; As[ac + 3][ar] = a0.w;
        As[ac + 4][ar] = a1.x; As[ac + 5][ar] = a1.y;
        As[ac + 6][ar] = a1.z; As[ac + 7][ar] = a1.w;
        *(float4*)&Bs[brw][bcol]     = bb0;
        *(float4*)&Bs[brw][bcol + 4] = bb1;
        __syncthreads();
#pragma unroll
        for (int kk = 0; kk < 16; kk++) {
            float a[8], b[8];
            *(float4*)&a[0] = *(const float4*)&As[kk][ty * 8];
            *(float4*)&a[4] = *(const float4*)&As[kk][ty * 8 + 4];
            *(float4*)&b[0] = *(const float4*)&Bs[kk][tx * 8];
            *(float4*)&b[4] = *(const float4*)&Bs[kk][tx * 8 + 4];
#pragma unroll
            for (int i = 0; i < 8; i++)
#pragma unroll
                for (int j = 0; j < 8; j++) acc[i][j] += a[i] * b[j];
        }
        __syncthreads();
    }

    const float* bz = b2 + (size_t)z * ND + n0 + tx * 8;
#pragma unroll
    for (int i = 0; i < 8; i++) {
        int r = m0 + ty * 8 + i;
        if (r < M) {
            int g = GATHER ? g_list[z * Tn + r] : r;
            float* orow = out + (size_t)g * Dn + n0 + tx * 8;
#pragma unroll
            for (int j = 0; j < 8; j++)
                atomicAdd(&orow[j], acc[i][j] + bz[j]);
        }
    }
}

extern "C" void kernel_launch(void* const* d_in, const int* in_sizes, int n_in,
                              void* d_out, int out_size) {
    const float* x   = (const float*)d_in[0];
    const float* Ws1 = (const float*)d_in[1];
    const float* bs1 = (const float*)d_in[2];
    const float* Ws2 = (const float*)d_in[3];
    const float* bs2 = (const float*)d_in[4];
    const float* We1 = (const float*)d_in[5];
    const float* be1 = (const float*)d_in[6];
    const float* We2 = (const float*)d_in[7];
    const float* be2 = (const float*)d_in[8];
    const float* Wr  = (const float*)d_in[9];
    const float* br  = (const float*)d_in[10];
    const float* gum = (const float*)d_in[11];
    float* out = (float*)d_out;

    cudaMemsetAsync(out, 0, (size_t)out_size * sizeof(float), 0);
    zero_cnt_kernel<<<1, 32>>>();
    router_kernel<<<Tn, 128>>>(x, Wr, br, gum);
    prefix_kernel<<<1, 32>>>();

    // Routed experts: only selected tokens (gathered). Grid covers worst case;
    // blocks beyond the runtime count exit immediately.
    ffn1_k<true><<<dim3(Hn / 128, Tn / 128, En), 256>>>(x, We1, be1);
    ffn2_k<true><<<dim3(Dn / 128, Tn / 128, En), 256>>>(We2, be2, out);

    // Shared experts: dense over all tokens.
    ffn1_k<false><<<dim3(Hn / 128, Tn / 128, NSn), 256>>>(x, Ws1, bs1);
    ffn2_k<false><<<dim3(Dn / 128, Tn / 128, NSn), 256>>>(Ws2, bs2, out);
}

// round 7
// speedup vs baseline: 2.9062x; 2.9062x over previous
#include <cuda_runtime.h>
#include <cuda_bf16.h>
#include <cstdint>
#include <math.h>

#define Tn 4096
#define Dn 1024
#define Hn 4096
#define En 8
#define NSn 2
#define NEn (En + NSn)
#define ROUTED_ROWS (2 * Tn)
#define ALLROWS (ROUTED_ROWS + NSn * Tn)

// ---- static scratch (no allocation APIs); aligned for cp.async 16B ----
__device__ __align__(1024) __nv_bfloat16 g_Xe[(size_t)Tn * 2 * Dn];      // x hi|lo [t][2D]
// Shared weight buffer: W1^T hi|lo [z][H][2D] during FFN1, then W2^T hi|lo [z][D][2H].
__device__ __align__(1024) __nv_bfloat16 g_We[(size_t)NEn * Hn * 2 * Dn];
__device__ __align__(1024) __nv_bfloat16 g_He[(size_t)ALLROWS * 2 * Hn]; // hidden hi|lo
__device__ int g_cnt[En];
__device__ int g_off[En];
__device__ int g_list[En * Tn];

// ---------------- PTX helpers (all non-'a' features: sm_80/75 era) ----------------
__device__ __forceinline__ uint32_t smem_u32(const void* p) {
    uint32_t a;
    asm("{ .reg .u64 t; cvta.to.shared.u64 t, %1; cvt.u32.u64 %0, t; }" : "=r"(a) : "l"(p));
    return a;
}
__device__ __forceinline__ void cp16(uint32_t s, const void* g) {
    asm volatile("cp.async.cg.shared.global [%0], [%1], 16;" :: "r"(s), "l"(g));
}
__device__ __forceinline__ void ldsm4(uint32_t* r, uint32_t a) {
    asm volatile("ldmatrix.sync.aligned.m8n8.x4.shared.b16 {%0,%1,%2,%3}, [%4];"
                 : "=r"(r[0]), "=r"(r[1]), "=r"(r[2]), "=r"(r[3]) : "r"(a));
}
__device__ __forceinline__ void mma16816(float* d, const uint32_t* a, uint32_t b0, uint32_t b1) {
    asm volatile(
        "mma.sync.aligned.m16n8k16.row.col.f32.bf16.bf16.f32 "
        "{%0,%1,%2,%3}, {%4,%5,%6,%7}, {%8,%9}, {%0,%1,%2,%3};"
        : "+f"(d[0]), "+f"(d[1]), "+f"(d[2]), "+f"(d[3])
        : "r"(a[0]), "r"(a[1]), "r"(a[2]), "r"(a[3]), "r"(b0), "r"(b1));
}
__device__ __forceinline__ float gelu_f(float v) {
    float u = 0.7978845608028654f * (v + 0.044715f * v * v * v);
    float t;
    asm("tanh.approx.f32 %0, %1;" : "=f"(t) : "f"(u));
    return 0.5f * v * (1.0f + t);
}

// ---------------- router ----------------
__global__ void zero_cnt_kernel() {
    if (threadIdx.x < En) g_cnt[threadIdx.x] = 0;
}
__global__ void prefix_kernel() {
    if (threadIdx.x == 0) {
        int s = 0;
#pragma unroll
        for (int e = 0; e < En; e++) { g_off[e] = s; s += g_cnt[e]; }
    }
}
__global__ void router_kernel(const float* __restrict__ x,
                              const float* __restrict__ Wr,
                              const float* __restrict__ br,
                              const float* __restrict__ gum) {
    int t = blockIdx.x;
    int tid = threadIdx.x;  // 128
    const float* xr = x + (size_t)t * Dn;
    float acc[En];
#pragma unroll
    for (int e = 0; e < En; e++) acc[e] = 0.f;
    for (int d = tid; d < Dn; d += 128) {
        float xv = xr[d];
        float4 w0 = *(const float4*)(Wr + d * En);
        float4 w1 = *(const float4*)(Wr + d * En + 4);
        acc[0] += xv * w0.x; acc[1] += xv * w0.y;
        acc[2] += xv * w0.z; acc[3] += xv * w0.w;
        acc[4] += xv * w1.x; acc[5] += xv * w1.y;
        acc[6] += xv * w1.z; acc[7] += xv * w1.w;
    }
#pragma unroll
    for (int e = 0; e < En; e++) {
#pragma unroll
        for (int off = 16; off; off >>= 1)
            acc[e] += __shfl_down_sync(0xffffffffu, acc[e], off);
    }
    __shared__ float red[4][En];
    if ((tid & 31) == 0) {
#pragma unroll
        for (int e = 0; e < En; e++) red[tid >> 5][e] = acc[e];
    }
    __syncthreads();
    if (tid == 0) {
        float s[En];
#pragma unroll
        for (int e = 0; e < En; e++)
            s[e] = red[0][e] + red[1][e] + red[2][e] + red[3][e]
                 + br[e] + gum[(size_t)t * En + e];
        int i1 = 0;
#pragma unroll
        for (int e = 1; e < En; e++) if (s[e] > s[i1]) i1 = e;
        int i2 = (i1 == 0) ? 1 : 0;
#pragma unroll
        for (int e = 0; e < En; e++)
            if (e != i1 && s[e] > s[i2]) i2 = e;
        int p1 = atomicAdd(&g_cnt[i1], 1); g_list[i1 * Tn + p1] = t;
        int p2 = atomicAdd(&g_cnt[i2], 1); g_list[i2 * Tn + p2] = t;
    }
}

// ---------------- hi/lo conversions ----------------
__global__ void ext_x_kernel(const float* __restrict__ x) {
    int idx = blockIdx.x * 256 + threadIdx.x;
    if (idx >= Tn * Dn) return;
    int t = idx / Dn, d = idx - t * Dn;
    float v = x[idx];
    __nv_bfloat16 hi = __float2bfloat16(v);
    g_Xe[(size_t)t * (2 * Dn) + d] = hi;
    g_Xe[(size_t)t * (2 * Dn) + Dn + d] = __float2bfloat16(v - __bfloat162float(hi));
}

// Transpose + split: src [z][SK][SN] fp32 -> g_We [zBase+z][SN][2*SK] bf16 (hi @ +0, lo @ +SK)
template <int SK, int SN>
__global__ void ext_w_kernel(const float* __restrict__ W, int zBase) {
    __shared__ float tile[32][33];
    int n0 = blockIdx.x * 32, k0 = blockIdx.y * 32;
    const float* Wz = W + (size_t)blockIdx.z * SK * SN;
    __nv_bfloat16* dst = g_We + (size_t)(zBase + blockIdx.z) * SN * (size_t)(2 * SK);
    int tx = threadIdx.x, ty = threadIdx.y;
#pragma unroll
    for (int r = 0; r < 32; r += 8)
        tile[ty + r][tx] = Wz[(size_t)(k0 + ty + r) * SN + n0 + tx];
    __syncthreads();
#pragma unroll
    for (int r = 0; r < 32; r += 8) {
        float v = tile[tx][ty + r];
        __nv_bfloat16 hi = __float2bfloat16(v);
        size_t o = (size_t)(n0 + ty + r) * (2 * SK) + (k0 + tx);
        dst[o] = hi;
        dst[o + SK] = __float2bfloat16(v - __bfloat162float(hi));
    }
}

// ---------------- mma.sync GEMM ----------------
#define BM 128
#define BN 128
#define BK 32
#define STAGES 3
#define ROWPB 80                      // padded row pitch in bytes (40 bf16)
#define TILEB (128 * ROWPB)           // 10240 B per operand tile
#define STGB (2 * TILEB)              // 20480 B per stage
#define SMEMT (STAGES * STGB)         // 61440 B

// IS1: He[row] = split(gelu(X@W1+b1));  !IS1: out[tok] += H@W2+b2
template <int KD, int NT, bool GATHER, bool IS1>
__global__ void __launch_bounds__(256, 2)
moe_gemm(const float* __restrict__ bias, float* __restrict__ outF) {
    int z = blockIdx.z;
    int M = GATHER ? g_cnt[z] : Tn;
    int m0 = blockIdx.y * BM;
    if (m0 >= M) return;
    int n0 = blockIdx.x * BN;
    int tid = threadIdx.x, lane = tid & 31, wid = tid >> 5;
    int wm = wid & 3, wn = wid >> 2;     // 4 x 2 warp grid; warp tile 32m x 64n

    extern __shared__ __align__(1024) char smem[];
    uint32_t sb = smem_u32(smem);

    size_t rowBase = GATHER ? (size_t)g_off[z] : (size_t)(ROUTED_ROWS + (size_t)z * Tn);
    // loader: row = tid>>1, two 16B chunks at bf16 cols (tid&1)*16 + {0,8}
    int arow = m0 + (tid >> 1);
    int rr = (arow < M) ? arow : (M - 1);
    const __nv_bfloat16* aRow;
    if (IS1) {
        int tok = GATHER ? g_list[z * Tn + rr] : rr;
        aRow = g_Xe + (size_t)tok * (2 * KD);
    } else {
        aRow = g_He + (rowBase + rr) * (size_t)(2 * KD);
    }
    int zw = GATHER ? z : (En + z);
    const __nv_bfloat16* bRowW = g_We + ((size_t)zw * NT + n0 + (tid >> 1)) * (size_t)(2 * KD);

    const int IT = KD / BK;
    const int nIter = 3 * IT;   // segments: Ah*Bh, Al*Bh, Ah*Bl
    uint32_t stBase = sb + (tid >> 1) * ROWPB + (tid & 1) * 32;
    int ldCol = (tid & 1) * 16;

    float d[2][8][4];
#pragma unroll
    for (int a = 0; a < 2; a++)
#pragma unroll
        for (int b = 0; b < 8; b++)
#pragma unroll
            for (int c = 0; c < 4; c++) d[a][b][c] = 0.f;

    auto loadStage = [&](int j, int s) {
        int seg = j / IT, kk = j - seg * IT;
        int aOff = ((seg == 1) ? KD : 0) + kk * BK + ldCol;
        int bOff = ((seg == 2) ? KD : 0) + kk * BK + ldCol;
        uint32_t sa = stBase + s * STGB;
        cp16(sa,      aRow + aOff);
        cp16(sa + 16, aRow + aOff + 8);
        uint32_t sB = sa + TILEB;
        cp16(sB,      bRowW + bOff);
        cp16(sB + 16, bRowW + bOff + 8);
    };

    loadStage(0, 0);
    asm volatile("cp.async.commit_group;" ::: "memory");
    loadStage(1, 1);
    asm volatile("cp.async.commit_group;" ::: "memory");

    // ldmatrix lane addressing
    int lrow = lane & 15, lcol = (lane >> 4) * 16;
    for (int j = 0; j < nIter; j++) {
        int s = j % STAGES;
        asm volatile("cp.async.wait_group 1;" ::: "memory");
        __syncthreads();
        int jn = j + 2;
        if (jn < nIter) loadStage(jn, jn % STAGES);
        asm volatile("cp.async.commit_group;" ::: "memory");

        uint32_t Ab = sb + s * STGB;
        uint32_t Bb = Ab + TILEB;
#pragma unroll
        for (int k16 = 0; k16 < 2; k16++) {
            uint32_t af[2][4];
#pragma unroll
            for (int mi = 0; mi < 2; mi++)
                ldsm4(af[mi], Ab + (wm * 32 + mi * 16 + lrow) * ROWPB + k16 * 32 + lcol);
            uint32_t bf[4][4];
#pragma unroll
            for (int g = 0; g < 4; g++)
                ldsm4(bf[g], Bb + (wn * 64 + g * 16 + lrow) * ROWPB + k16 * 32 + lcol);
#pragma unroll
            for (int mi = 0; mi < 2; mi++)
#pragma unroll
                for (int t = 0; t < 8; t++) {
                    int g = t >> 1, w = t & 1;
                    mma16816(d[mi][t], af[mi], bf[g][w], bf[g][2 + w]);
                }
        }
    }

    // ---- epilogue ----
    const float* bz = bias + (size_t)z * NT;
    int cb = n0 + wn * 64 + (lane & 3) * 2;
    int r0 = m0 + wm * 32 + (lane >> 2);
#pragma unroll
    for (int mi = 0; mi < 2; mi++) {
#pragma unroll
        for (int half = 0; half < 2; half++) {   // regs {0,1} row r, {2,3} row r+8
            int row = r0 + mi * 16 + half * 8;
            if (row >= M) continue;
            if (IS1) {
                __nv_bfloat16* dstH = g_He + (rowBase + row) * (size_t)(2 * NT);
#pragma unroll
                for (int ni = 0; ni < 8; ni++) {
                    int col = cb + ni * 8;
                    float v0 = gelu_f(d[mi][ni][half * 2 + 0] + bz[col]);
                    float v1 = gelu_f(d[mi][ni][half * 2 + 1] + bz[col + 1]);
                    __nv_bfloat16 h0 = __float2bfloat16(v0);
                    __nv_bfloat16 h1 = __float2bfloat16(v1);
                    __nv_bfloat16 l0 = __float2bfloat16(v0 - __bfloat162float(h0));
                    __nv_bfloat16 l1 = __float2bfloat16(v1 - __bfloat162float(h1));
                    uint32_t ph = ((uint32_t)*(uint16_t*)&h1 << 16) | *(uint16_t*)&h0;
                    uint32_t pl = ((uint32_t)*(uint16_t*)&l1 << 16) | *(uint16_t*)&l0;
                    *(uint32_t*)(dstH + col) = ph;
                    *(uint32_t*)(dstH + NT + col) = pl;
                }
            } else {
                int g = GATHER ? g_list[z * Tn + row] : row;
                float* od = outF + (size_t)g * Dn;
#pragma unroll
                for (int ni = 0; ni < 8; ni++) {
                    int col = cb + ni * 8;
                    atomicAdd(&od[col],     d[mi][ni][half * 2 + 0] + bz[col]);
                    atomicAdd(&od[col + 1], d[mi][ni][half * 2 + 1] + bz[col + 1]);
                }
            }
        }
    }
}

extern "C" void kernel_launch(void* const* d_in, const int* in_sizes, int n_in,
                              void* d_out, int out_size) {
    const float* x   = (const float*)d_in[0];
    const float* Ws1 = (const float*)d_in[1];
    const float* bs1 = (const float*)d_in[2];
    const float* Ws2 = (const float*)d_in[3];
    const float* bs2 = (const float*)d_in[4];
    const float* We1 = (const float*)d_in[5];
    const float* be1 = (const float*)d_in[6];
    const float* We2 = (const float*)d_in[7];
    const float* be2 = (const float*)d_in[8];
    const float* Wr  = (const float*)d_in[9];
    const float* br  = (const float*)d_in[10];
    const float* gum = (const float*)d_in[11];
    float* out = (float*)d_out;

    cudaFuncSetAttribute(moe_gemm<Dn, Hn, true,  true >, cudaFuncAttributeMaxDynamicSharedMemorySize, SMEMT);
    cudaFuncSetAttribute(moe_gemm<Dn, Hn, false, true >, cudaFuncAttributeMaxDynamicSharedMemorySize, SMEMT);
    cudaFuncSetAttribute(moe_gemm<Hn, Dn, true,  false>, cudaFuncAttributeMaxDynamicSharedMemorySize, SMEMT);
    cudaFuncSetAttribute(moe_gemm<Hn, Dn, false, false>, cudaFuncAttributeMaxDynamicSharedMemorySize, SMEMT);

    cudaMemsetAsync(out, 0, (size_t)out_size * sizeof(float), 0);
    zero_cnt_kernel<<<1, 32>>>();
    router_kernel<<<Tn, 128>>>(x, Wr, br, gum);
    prefix_kernel<<<1, 32>>>();

    ext_x_kernel<<<(Tn * Dn) / 256, 256>>>(x);
    dim3 bw(32, 8);

    // Phase 1: W1^T into g_We, then FFN1 (routed + shared).
    ext_w_kernel<Dn, Hn><<<dim3(Hn / 32, Dn / 32, En ), bw>>>(We1, 0);
    ext_w_kernel<Dn, Hn><<<dim3(Hn / 32, Dn / 32, NSn), bw>>>(Ws1, En);
    moe_gemm<Dn, Hn, true,  true ><<<dim3(Hn / BN, Tn / BM, En ), 256, SMEMT>>>(be1, nullptr);
    moe_gemm<Dn, Hn, false, true ><<<dim3(Hn / BN, Tn / BM, NSn), 256, SMEMT>>>(bs1, nullptr);

    // Phase 2: W2^T overwrites g_We (stream-ordered after FFN1), then FFN2.
    ext_w_kernel<Hn, Dn><<<dim3(Dn / 32, Hn / 32, En ), bw>>>(We2, 0);
    ext_w_kernel<Hn, Dn><<<dim3(Dn / 32, Hn / 32, NSn), bw>>>(Ws2, En);
    moe_gemm<Hn, Dn, true,  false><<<dim3(Dn / BN, Tn / BM, En ), 256, SMEMT>>>(be2, out);
    moe_gemm<Hn, Dn, false, false><<<dim3(Dn / BN, Tn / BM, NSn), 256, SMEMT>>>(bs2, out);
}